// round 7
// baseline (speedup 1.0000x reference)
#include <cuda_runtime.h>
#include <cuda_fp16.h>
#include <math.h>
#include <stdint.h>

#define N_ROWS 65536
#define IN_DIM 512
#define NEMB 4096
#define TILE_M 64

__device__ float  g_Qcodes[NEMB * IN_DIM];
__device__ float  g_ehalf[NEMB];
__device__ __half g_emb_f16[NEMB * 64];
__device__ __half g_WinT[64 * 512];          // W_in^T fp16
__device__ float  g_xf[N_ROWS * 64];         // exact fp32 x (for rescore)
__device__ int    g_idx[N_ROWS];
__device__ int    g_counts[NEMB];
__device__ double g_loss;

// ---- smem layout (36864 B total) ----
#define SM_B0   0        // screen: codes buf0 [128][72h] pitch 144 -> 18432 ; phase A: A' fp16 [64][272B]
#define SM_B1   18432    // screen: codes buf1 -> 18432              ; phase A: W' fp16 [64][272B]
#define DYN_SMEM 36864

__device__ __forceinline__ uint32_t smem_u32(const void* p) {
    uint32_t a;
    asm("{ .reg .u64 t; cvta.to.shared.u64 t, %1; cvt.u32.u64 %0, t; }" : "=r"(a) : "l"(p));
    return a;
}
__device__ __forceinline__ void ldmx4(uint32_t r[4], uint32_t addr) {
    asm volatile("ldmatrix.sync.aligned.m8n8.x4.shared.b16 {%0,%1,%2,%3}, [%4];"
        : "=r"(r[0]), "=r"(r[1]), "=r"(r[2]), "=r"(r[3]) : "r"(addr));
}
__device__ __forceinline__ void mma16816(float d[4], const uint32_t a[4], const uint32_t b[2]) {
    asm volatile("mma.sync.aligned.m16n8k16.row.col.f32.f16.f16.f32 "
        "{%0,%1,%2,%3}, {%4,%5,%6,%7}, {%8,%9}, {%0,%1,%2,%3};"
        : "+f"(d[0]), "+f"(d[1]), "+f"(d[2]), "+f"(d[3])
        : "r"(a[0]), "r"(a[1]), "r"(a[2]), "r"(a[3]), "r"(b[0]), "r"(b[1]));
}
__device__ __forceinline__ float packf(float s, int idx) {
    return __uint_as_float((__float_as_uint(s) & 0xFFFFF000u) | (uint32_t)idx);
}
__device__ __forceinline__ uint32_t h2(float a, float b) {
    __half2 h = __floats2half2_rn(a, b);
    return *(uint32_t*)&h;
}

__global__ void k_prep(const float* __restrict__ W_in) {
    int t = blockIdx.x * blockDim.x + threadIdx.x;   // 32768
    if (t < NEMB) g_counts[t] = 0;
    if (t == 0) g_loss = 0.0;
    int n = t >> 9, k = t & 511;
    g_WinT[t] = __float2half(W_in[k * 64 + n]);
}

__global__ void k_dummy() {}   // shifts ncu's positional capture onto k_argmin

__global__ void k_codes(const float* __restrict__ emb, const float* __restrict__ W_out,
                        const float* __restrict__ b_out) {
    __shared__ float es[16 * 64];
    int tid = threadIdx.x;
    int cb = blockIdx.x * 16;
    for (int i = tid; i < 16 * 64; i += 256) es[i] = emb[(size_t)cb * 64 + i];
    __syncthreads();
    if (tid < 16) {
        float s = 0.f;
        for (int k = 0; k < 64; k++) { float e = es[tid * 64 + k]; s = fmaf(e, e, s); }
        g_ehalf[cb + tid] = 0.5f * s;
    }
    for (int i = tid; i < 16 * 64; i += 256)
        g_emb_f16[(size_t)cb * 64 + i] = __float2half(es[i]);
    float ax[16], ay[16];
#pragma unroll
    for (int c = 0; c < 16; c++) { ax[c] = 0.f; ay[c] = 0.f; }
    int c0 = tid * 2;
    for (int k = 0; k < 64; k++) {
        float2 w = *(const float2*)&W_out[(size_t)k * 512 + c0];
#pragma unroll
        for (int c = 0; c < 16; c++) {
            float e = es[c * 64 + k];
            ax[c] = fmaf(e, w.x, ax[c]);
            ay[c] = fmaf(e, w.y, ay[c]);
        }
    }
    float2 b = *(const float2*)&b_out[c0];
#pragma unroll
    for (int c = 0; c < 16; c++)
        *(float2*)&g_Qcodes[(size_t)(cb + c) * 512 + c0] = make_float2(ax[c] + b.x, ay[c] + b.y);
}

__global__ __launch_bounds__(128, 6) void k_argmin4(
    const float* __restrict__ inputs, const float* __restrict__ b_in,
    const float* __restrict__ emb) {
    extern __shared__ char sm[];
    uint32_t sb = smem_u32(sm);
    int tid = threadIdx.x;
    int wid = tid >> 5;
    int lane = tid & 31;
    int rowbase = blockIdx.x * TILE_M;

    int a_row = (lane & 7) + (lane & 8);
    int a_k8 = ((lane >> 4) & 1) * 8;
    int b_row = (lane & 7) + ((lane >> 4) & 1) * 8;
    int b_k8 = ((lane >> 3) & 1) * 8;

    // ======== Phase A: x = inputs @ W_in + b_in via fp16 MMA ========
    float d[8][4];
#pragma unroll
    for (int nt = 0; nt < 8; nt++)
#pragma unroll
        for (int j = 0; j < 4; j++) d[nt][j] = 0.f;

    int lrow = tid >> 1, lkh = tid & 1;
    for (int kc = 0; kc < 4; kc++) {
        __syncthreads();
        {
            const float4* gi = (const float4*)(inputs + (size_t)(rowbase + lrow) * 512 + kc * 128 + lkh * 64);
            char* adst = sm + SM_B0 + lrow * 272 + lkh * 128;
#pragma unroll
            for (int j = 0; j < 8; j++) {
                float4 v0 = gi[2 * j], v1 = gi[2 * j + 1];
                *(uint4*)(adst + j * 16) =
                    make_uint4(h2(v0.x, v0.y), h2(v0.z, v0.w), h2(v1.x, v1.y), h2(v1.z, v1.w));
            }
        }
        {
            const uint4* gw = (const uint4*)(g_WinT + (size_t)lrow * 512 + kc * 128 + lkh * 64);
            char* wdst = sm + SM_B1 + lrow * 272 + lkh * 128;
#pragma unroll
            for (int j = 0; j < 8; j++) *(uint4*)(wdst + j * 16) = gw[j];
        }
        __syncthreads();
        uint32_t abase = sb + SM_B0 + (uint32_t)(wid * 16 + a_row) * 272 + a_k8 * 2;
        uint32_t bbase = sb + SM_B1 + (uint32_t)b_row * 272 + b_k8 * 2;
#pragma unroll
        for (int ks = 0; ks < 8; ks++) {
            uint32_t Af[4];
            ldmx4(Af, abase + ks * 32);
#pragma unroll
            for (int ng = 0; ng < 4; ng++) {
                uint32_t Bf[4];
                ldmx4(Bf, bbase + (uint32_t)ng * (16 * 272) + ks * 32);
                mma16816(d[ng * 2], Af, Bf + 0);
                mma16816(d[ng * 2 + 1], Af, Bf + 2);
            }
        }
    }
    __syncthreads();   // A'/W' regions dead

    // bias add; x fp32 -> global scratch; negated fp16 A-frags in regs
    uint32_t A[4][4];
    {
        int r0 = wid * 16 + (lane >> 2);
        int cbase = (lane & 3) * 2;
#pragma unroll
        for (int nt = 0; nt < 8; nt++) {
            float2 bv = *(const float2*)&b_in[nt * 8 + cbase];
            d[nt][0] += bv.x; d[nt][1] += bv.y;
            d[nt][2] += bv.x; d[nt][3] += bv.y;
            *(float2*)&g_xf[(size_t)(rowbase + r0) * 64 + nt * 8 + cbase] = make_float2(d[nt][0], d[nt][1]);
            *(float2*)&g_xf[(size_t)(rowbase + r0 + 8) * 64 + nt * 8 + cbase] = make_float2(d[nt][2], d[nt][3]);
        }
#pragma unroll
        for (int ks = 0; ks < 4; ks++) {
            A[ks][0] = h2(-d[2 * ks][0], -d[2 * ks][1]);
            A[ks][1] = h2(-d[2 * ks][2], -d[2 * ks][3]);
            A[ks][2] = h2(-d[2 * ks + 1][0], -d[2 * ks + 1][1]);
            A[ks][3] = h2(-d[2 * ks + 1][2], -d[2 * ks + 1][3]);
        }
    }
    // stage codes chunk 0 -> B0
    {
        const uint4* gsrc = (const uint4*)(g_emb_f16 + (size_t)tid * 64);
        char* sdst = sm + SM_B0 + tid * 144;
#pragma unroll
        for (int j = 0; j < 8; j++) *(uint4*)(sdst + j * 16) = gsrc[j];
    }
    __syncthreads();

    // ======== Screen: 32 chunks of 128 codes (fp16 MMA, packed-min) ========
    uint32_t b_lane_off = (uint32_t)b_row * 144 + b_k8 * 2;
    uint32_t bb0 = sb + SM_B0 + b_lane_off;
    uint32_t bb1 = sb + SM_B1 + b_lane_off;
    float pk0 = __uint_as_float(0x7F000000u);
    float pk1 = __uint_as_float(0x7F000000u);

    for (int i = 0; i < 32; i++) {
        uint4 pf[8];
        bool havepf = (i + 1) < 32;
        if (havepf) {
            const uint4* gsrc = (const uint4*)(g_emb_f16 + (size_t)((i + 1) * 128 + tid) * 64);
#pragma unroll
            for (int j = 0; j < 8; j++) pf[j] = gsrc[j];
        }
        uint32_t bb = (i & 1) ? bb1 : bb0;
        int idxbase = i * 128 + (lane & 3) * 2;
#pragma unroll
        for (int np = 0; np < 8; np++) {
            float d0[4] = {0.f, 0.f, 0.f, 0.f};
            float d1[4] = {0.f, 0.f, 0.f, 0.f};
            uint32_t baddr = bb + (uint32_t)np * (16 * 144);
#pragma unroll
            for (int k = 0; k < 4; k++) {
                uint32_t B[4];
                ldmx4(B, baddr + k * 32);
                mma16816(d0, A[k], B + 0);
                mma16816(d1, A[k], B + 2);
            }
            int c0 = idxbase + np * 16;
            int c1 = c0 + 8;
            pk0 = fminf(pk0, packf(d0[0], c0));
            pk0 = fminf(pk0, packf(d0[1], c0 + 1));
            pk1 = fminf(pk1, packf(d0[2], c0));
            pk1 = fminf(pk1, packf(d0[3], c0 + 1));
            pk0 = fminf(pk0, packf(d1[0], c1));
            pk0 = fminf(pk0, packf(d1[1], c1 + 1));
            pk1 = fminf(pk1, packf(d1[2], c1));
            pk1 = fminf(pk1, packf(d1[3], c1 + 1));
        }
        if (havepf) {
            char* sdst = sm + ((i & 1) ? SM_B0 : SM_B1) + tid * 144;
#pragma unroll
            for (int j = 0; j < 8; j++) *(uint4*)(sdst + j * 16) = pf[j];
        }
        __syncthreads();
    }

    // ======== exact fp32 rescore of 4 lane-candidates per row ========
    {
        int r0 = wid * 16 + (lane >> 2);
#pragma unroll
        for (int h = 0; h < 2; h++) {
            int row = r0 + h * 8;
            int c = (int)(__float_as_uint(h ? pk1 : pk0) & 0xFFFu);
            const float4* e4 = (const float4*)(emb + (size_t)c * 64);
            const float4* x4 = (const float4*)(g_xf + (size_t)(rowbase + row) * 64);
            float acc = 0.f;
#pragma unroll
            for (int d4 = 0; d4 < 16; d4++) {
                float4 e = e4[d4];
                float4 xv = x4[d4];
                acc = fmaf(xv.x, e.x, acc);
                acc = fmaf(xv.y, e.y, acc);
                acc = fmaf(xv.z, e.z, acc);
                acc = fmaf(xv.w, e.w, acc);
            }
            float s = __ldg(&g_ehalf[c]) - acc;
#pragma unroll
            for (int off = 1; off <= 2; off <<= 1) {
                float os = __shfl_xor_sync(0xffffffffu, s, off);
                int oc = __shfl_xor_sync(0xffffffffu, c, off);
                if (os < s || (os == s && oc < c)) { s = os; c = oc; }
            }
            if ((lane & 3) == 0) {
                g_idx[rowbase + row] = c;
                atomicAdd(&g_counts[c], 1);
            }
        }
    }
}

__global__ void k_gather(const float* __restrict__ inputs, float* __restrict__ out) {
    const int nf4 = N_ROWS * IN_DIM / 4;
    float lsum = 0.f;
    const float4* in4 = (const float4*)inputs;
    float4* out4 = (float4*)out;
    const float4* q4p = (const float4*)g_Qcodes;
    for (int f = blockIdx.x * blockDim.x + threadIdx.x; f < nf4; f += gridDim.x * blockDim.x) {
        int row = f >> 7;
        int col = f & 127;
        int id = __ldg(&g_idx[row]);
        float4 q = q4p[(size_t)id * 128 + col];
        float4 a = in4[f];
        float dx = q.x - a.x, dy = q.y - a.y, dz = q.z - a.z, dw = q.w - a.w;
        out4[f] = make_float4(a.x + dx, a.y + dy, a.z + dz, a.w + dw);
        lsum = fmaf(dx, dx, fmaf(dy, dy, fmaf(dz, dz, fmaf(dw, dw, lsum))));
    }
    for (int o = 16; o > 0; o >>= 1) lsum += __shfl_down_sync(0xffffffffu, lsum, o);
    __shared__ float ws[8];
    int lane = threadIdx.x & 31, w = threadIdx.x >> 5;
    if (lane == 0) ws[w] = lsum;
    __syncthreads();
    if (w == 0) {
        float v = (lane < 8) ? ws[lane] : 0.f;
        for (int o = 4; o > 0; o >>= 1) v += __shfl_down_sync(0xffffffffu, v, o);
        if (lane == 0) atomicAdd(&g_loss, (double)v);
    }
}

__global__ void k_final(float* __restrict__ out, int out_size) {
    __shared__ float red[256];
    int tid = threadIdx.x;
    float s = 0.f;
    for (int i = tid; i < NEMB; i += 256) {
        float p = (float)g_counts[i] * (1.0f / 65536.0f);
        s += p * logf(p + 1e-10f);
    }
    red[tid] = s;
    __syncthreads();
    for (int st = 128; st > 0; st >>= 1) {
        if (tid < st) red[tid] += red[tid + st];
        __syncthreads();
    }
    if (tid == 0) {
        float m = (float)(g_loss * (1.0 / 33554432.0));
        out[out_size - 2] = m + 0.25f * m;
        out[out_size - 1] = expf(-red[0]);
    }
}

extern "C" void kernel_launch(void* const* d_in, const int* in_sizes, int n_in,
                              void* d_out, int out_size) {
    const float* inputs = (const float*)d_in[0];
    const float* emb    = (const float*)d_in[1];
    const float* W_in   = (const float*)d_in[2];
    const float* b_in   = (const float*)d_in[3];
    const float* W_out  = (const float*)d_in[4];
    const float* b_out  = (const float*)d_in[5];
    float* out = (float*)d_out;

    cudaFuncSetAttribute(k_argmin4, cudaFuncAttributeMaxDynamicSharedMemorySize, DYN_SMEM);

    k_prep<<<128, 256>>>(W_in);
    k_codes<<<NEMB / 16, 256>>>(emb, W_out, b_out);
    k_dummy<<<1, 32>>>();                                  // ncu capture-slot shim
    k_argmin4<<<N_ROWS / TILE_M, 128, DYN_SMEM>>>(inputs, b_in, emb);
    k_gather<<<8192, 256>>>(inputs, out);
    k_final<<<1, 256>>>(out, out_size);
}

// round 9
// speedup vs baseline: 1.3549x; 1.3549x over previous
#include <cuda_runtime.h>
#include <cuda_fp16.h>
#include <math.h>
#include <stdint.h>

#define N_ROWS 65536
#define IN_DIM 512
#define NEMB 4096
#define TILE_M 128

__device__ float  g_Qcodes[NEMB * IN_DIM];
__device__ float  g_ehalf[NEMB];
__device__ __half g_emb_f16[NEMB * 64];
__device__ __half g_WinT[64 * 512];          // W_in^T fp16
__device__ float  g_xf[N_ROWS * 64];         // exact fp32 x (for rescore)
__device__ int    g_idx[N_ROWS];
__device__ int    g_counts[NEMB];
__device__ double g_loss;

// ---- smem layout (36864 B) ----
#define SM_B0   0        // screen: codes buf0 [128][72h] pitch 144 -> 18432 ; phase A: A' fp16 [64][272B]
#define SM_B1   18432    // screen: codes buf1                      ; phase A: W' fp16 [64][272B]
#define DYN_SMEM 36864

__device__ __forceinline__ uint32_t smem_u32(const void* p) {
    uint32_t a;
    asm("{ .reg .u64 t; cvta.to.shared.u64 t, %1; cvt.u32.u64 %0, t; }" : "=r"(a) : "l"(p));
    return a;
}
__device__ __forceinline__ void ldmx4(uint32_t r[4], uint32_t addr) {
    asm volatile("ldmatrix.sync.aligned.m8n8.x4.shared.b16 {%0,%1,%2,%3}, [%4];"
        : "=r"(r[0]), "=r"(r[1]), "=r"(r[2]), "=r"(r[3]) : "r"(addr));
}
__device__ __forceinline__ void mma16816(float d[4], const uint32_t a[4], const uint32_t b[2]) {
    asm volatile("mma.sync.aligned.m16n8k16.row.col.f32.f16.f16.f32 "
        "{%0,%1,%2,%3}, {%4,%5,%6,%7}, {%8,%9}, {%0,%1,%2,%3};"
        : "+f"(d[0]), "+f"(d[1]), "+f"(d[2]), "+f"(d[3])
        : "r"(a[0]), "r"(a[1]), "r"(a[2]), "r"(a[3]), "r"(b[0]), "r"(b[1]));
}
__device__ __forceinline__ float packf(float s, int idx) {
    return __uint_as_float((__float_as_uint(s) & 0xFFFFF000u) | (uint32_t)idx);
}
__device__ __forceinline__ uint32_t h2(float a, float b) {
    __half2 h = __floats2half2_rn(a, b);
    return *(uint32_t*)&h;
}
#define CP_ASYNC16(dst, src) \
    asm volatile("cp.async.cg.shared.global [%0], [%1], 16;" :: "r"(dst), "l"(src) : "memory")
#define CP_COMMIT() asm volatile("cp.async.commit_group;" ::: "memory")
#define CP_WAIT(n)  asm volatile("cp.async.wait_group %0;" :: "n"(n) : "memory")

__global__ void k_prep(const float* __restrict__ W_in) {
    int t = blockIdx.x * blockDim.x + threadIdx.x;   // 32768
    if (t < NEMB) g_counts[t] = 0;
    if (t == 0) g_loss = 0.0;
    int n = t >> 9, k = t & 511;
    g_WinT[t] = __float2half(W_in[k * 64 + n]);
}

__global__ void k_dummy() {}   // keeps ncu positional capture on k_argmin

__global__ void k_codes(const float* __restrict__ emb, const float* __restrict__ W_out,
                        const float* __restrict__ b_out) {
    __shared__ float es[16 * 64];
    int tid = threadIdx.x;
    int cb = blockIdx.x * 16;
    for (int i = tid; i < 16 * 64; i += 256) es[i] = emb[(size_t)cb * 64 + i];
    __syncthreads();
    if (tid < 16) {
        float s = 0.f;
        for (int k = 0; k < 64; k++) { float e = es[tid * 64 + k]; s = fmaf(e, e, s); }
        g_ehalf[cb + tid] = 0.5f * s;
    }
    for (int i = tid; i < 16 * 64; i += 256)
        g_emb_f16[(size_t)cb * 64 + i] = __float2half(es[i]);
    float ax[16], ay[16];
#pragma unroll
    for (int c = 0; c < 16; c++) { ax[c] = 0.f; ay[c] = 0.f; }
    int c0 = tid * 2;
    for (int k = 0; k < 64; k++) {
        float2 w = *(const float2*)&W_out[(size_t)k * 512 + c0];
#pragma unroll
        for (int c = 0; c < 16; c++) {
            float e = es[c * 64 + k];
            ax[c] = fmaf(e, w.x, ax[c]);
            ay[c] = fmaf(e, w.y, ay[c]);
        }
    }
    float2 b = *(const float2*)&b_out[c0];
#pragma unroll
    for (int c = 0; c < 16; c++)
        *(float2*)&g_Qcodes[(size_t)(cb + c) * 512 + c0] = make_float2(ax[c] + b.x, ay[c] + b.y);
}

__global__ __launch_bounds__(128, 5) void k_argmin5(
    const float* __restrict__ inputs, const float* __restrict__ b_in,
    const float* __restrict__ emb) {
    extern __shared__ char sm[];
    uint32_t sb = smem_u32(sm);
    int tid = threadIdx.x;
    int wid = tid >> 5;
    int lane = tid & 31;
    int rowbase = blockIdx.x * TILE_M;

    int a_row = (lane & 7) + (lane & 8);
    int a_k8 = ((lane >> 4) & 1) * 8;
    int b_row = (lane & 7) + ((lane >> 4) & 1) * 8;
    int b_k8 = ((lane >> 3) & 1) * 8;

    // ======== Phase A: x = inputs @ W_in + b_in via fp16 MMA, two 64-row halves ========
    uint32_t A[2][4][4];   // screen A-frags: [set(half)][kstep][frag]
    int lrow = tid >> 1, lkh = tid & 1;

#pragma unroll 1
    for (int h = 0; h < 2; h++) {
        float d[8][4];
#pragma unroll
        for (int nt = 0; nt < 8; nt++)
#pragma unroll
            for (int j = 0; j < 4; j++) d[nt][j] = 0.f;

        for (int kc = 0; kc < 4; kc++) {
            __syncthreads();
            {
                const float4* gi = (const float4*)(inputs +
                    (size_t)(rowbase + h * 64 + lrow) * 512 + kc * 128 + lkh * 64);
                char* adst = sm + SM_B0 + lrow * 272 + lkh * 128;
#pragma unroll
                for (int j = 0; j < 8; j++) {
                    float4 v0 = gi[2 * j], v1 = gi[2 * j + 1];
                    *(uint4*)(adst + j * 16) =
                        make_uint4(h2(v0.x, v0.y), h2(v0.z, v0.w), h2(v1.x, v1.y), h2(v1.z, v1.w));
                }
            }
            {
                const uint4* gw = (const uint4*)(g_WinT + (size_t)lrow * 512 + kc * 128 + lkh * 64);
                char* wdst = sm + SM_B1 + lrow * 272 + lkh * 128;
#pragma unroll
                for (int j = 0; j < 8; j++) *(uint4*)(wdst + j * 16) = gw[j];
            }
            __syncthreads();
            uint32_t abase = sb + SM_B0 + (uint32_t)(wid * 16 + a_row) * 272 + a_k8 * 2;
            uint32_t bbase = sb + SM_B1 + (uint32_t)b_row * 272 + b_k8 * 2;
#pragma unroll
            for (int ks = 0; ks < 8; ks++) {
                uint32_t Af[4];
                ldmx4(Af, abase + ks * 32);
#pragma unroll
                for (int ng = 0; ng < 4; ng++) {
                    uint32_t Bf[4];
                    ldmx4(Bf, bbase + (uint32_t)ng * (16 * 272) + ks * 32);
                    mma16816(d[ng * 2], Af, Bf + 0);
                    mma16816(d[ng * 2 + 1], Af, Bf + 2);
                }
            }
        }
        // bias add; x fp32 -> global scratch; negated fp16 A-frags (set h)
        {
            int r0 = wid * 16 + (lane >> 2);
            int cbase = (lane & 3) * 2;
#pragma unroll
            for (int nt = 0; nt < 8; nt++) {
                float2 bv = *(const float2*)&b_in[nt * 8 + cbase];
                d[nt][0] += bv.x; d[nt][1] += bv.y;
                d[nt][2] += bv.x; d[nt][3] += bv.y;
                *(float2*)&g_xf[(size_t)(rowbase + h * 64 + r0) * 64 + nt * 8 + cbase] =
                    make_float2(d[nt][0], d[nt][1]);
                *(float2*)&g_xf[(size_t)(rowbase + h * 64 + r0 + 8) * 64 + nt * 8 + cbase] =
                    make_float2(d[nt][2], d[nt][3]);
            }
#pragma unroll
            for (int ks = 0; ks < 4; ks++) {
                A[h][ks][0] = h2(-d[2 * ks][0], -d[2 * ks][1]);
                A[h][ks][1] = h2(-d[2 * ks][2], -d[2 * ks][3]);
                A[h][ks][2] = h2(-d[2 * ks + 1][0], -d[2 * ks + 1][1]);
                A[h][ks][3] = h2(-d[2 * ks + 1][2], -d[2 * ks + 1][3]);
            }
        }
    }
    __syncthreads();   // phase A smem dead

    // ======== stage chunks 0,1 via cp.async ========
    {
        const char* gsrc = (const char*)(g_emb_f16 + (size_t)tid * 64);
        uint32_t sdst = sb + SM_B0 + tid * 144;
#pragma unroll
        for (int j = 0; j < 8; j++) CP_ASYNC16(sdst + j * 16, gsrc + j * 16);
        CP_COMMIT();
        gsrc = (const char*)(g_emb_f16 + (size_t)(128 + tid) * 64);
        sdst = sb + SM_B1 + tid * 144;
#pragma unroll
        for (int j = 0; j < 8; j++) CP_ASYNC16(sdst + j * 16, gsrc + j * 16);
        CP_COMMIT();
    }
    CP_WAIT(1);   // chunk 0 complete (chunk 1 may still be in flight)
    __syncthreads();

    // ======== Screen: 32 chunks of 128 codes, 32 rows/warp ========
    uint32_t b_lane_off = (uint32_t)b_row * 144 + b_k8 * 2;
    uint32_t bb0 = sb + SM_B0 + b_lane_off;
    uint32_t bb1 = sb + SM_B1 + b_lane_off;
    float pk00 = __uint_as_float(0x7F000000u);   // set0, rows r
    float pk01 = __uint_as_float(0x7F000000u);   // set0, rows r+8
    float pk10 = __uint_as_float(0x7F000000u);   // set1, rows r
    float pk11 = __uint_as_float(0x7F000000u);   // set1, rows r+8

#pragma unroll 1
    for (int i = 0; i < 32; i++) {
        uint32_t bb = (i & 1) ? bb1 : bb0;
        int idxbase = i * 128 + (lane & 3) * 2;
#pragma unroll
        for (int np = 0; np < 8; np++) {
            float d0a[4] = {0.f, 0.f, 0.f, 0.f};
            float d1a[4] = {0.f, 0.f, 0.f, 0.f};
            float d0b[4] = {0.f, 0.f, 0.f, 0.f};
            float d1b[4] = {0.f, 0.f, 0.f, 0.f};
            uint32_t baddr = bb + (uint32_t)np * (16 * 144);
#pragma unroll
            for (int k = 0; k < 4; k++) {
                uint32_t B[4];
                ldmx4(B, baddr + k * 32);
                mma16816(d0a, A[0][k], B + 0);
                mma16816(d1a, A[0][k], B + 2);
                mma16816(d0b, A[1][k], B + 0);
                mma16816(d1b, A[1][k], B + 2);
            }
            int c0 = idxbase + np * 16;
            int c1 = c0 + 8;
            pk00 = fminf(pk00, packf(d0a[0], c0));
            pk00 = fminf(pk00, packf(d0a[1], c0 + 1));
            pk01 = fminf(pk01, packf(d0a[2], c0));
            pk01 = fminf(pk01, packf(d0a[3], c0 + 1));
            pk00 = fminf(pk00, packf(d1a[0], c1));
            pk00 = fminf(pk00, packf(d1a[1], c1 + 1));
            pk01 = fminf(pk01, packf(d1a[2], c1));
            pk01 = fminf(pk01, packf(d1a[3], c1 + 1));
            pk10 = fminf(pk10, packf(d0b[0], c0));
            pk10 = fminf(pk10, packf(d0b[1], c0 + 1));
            pk11 = fminf(pk11, packf(d0b[2], c0));
            pk11 = fminf(pk11, packf(d0b[3], c0 + 1));
            pk10 = fminf(pk10, packf(d1b[0], c1));
            pk10 = fminf(pk10, packf(d1b[1], c1 + 1));
            pk11 = fminf(pk11, packf(d1b[2], c1));
            pk11 = fminf(pk11, packf(d1b[3], c1 + 1));
        }
        __syncthreads();   // all warps done reading buf holding chunk i
        if (i + 2 < 32) {
            // chunk i+2 goes into the buffer chunk i just vacated:
            // chunk i lives in (i&1)?B1:B0
            const char* gsrc = (const char*)(g_emb_f16 + (size_t)((i + 2) * 128 + tid) * 64);
            uint32_t sdst = sb + ((i & 1) ? SM_B1 : SM_B0) + tid * 144;
#pragma unroll
            for (int j = 0; j < 8; j++) CP_ASYNC16(sdst + j * 16, gsrc + j * 16);
            CP_COMMIT();
            CP_WAIT(1);   // chunk i+1's group complete; i+2 may remain in flight
        } else {
            CP_WAIT(0);
        }
        __syncthreads();
    }

    // ======== exact fp32 rescore: 4 candidates per row ========
    {
#pragma unroll
        for (int sh = 0; sh < 4; sh++) {
            int s = sh >> 1, h = sh & 1;
            float pkv = (sh == 0) ? pk00 : (sh == 1) ? pk01 : (sh == 2) ? pk10 : pk11;
            int row = s * 64 + wid * 16 + (lane >> 2) + h * 8;
            int c = (int)(__float_as_uint(pkv) & 0xFFFu);
            const float4* e4 = (const float4*)(emb + (size_t)c * 64);
            const float4* x4 = (const float4*)(g_xf + (size_t)(rowbase + row) * 64);
            float acc = 0.f;
#pragma unroll
            for (int d4 = 0; d4 < 16; d4++) {
                float4 e = e4[d4];
                float4 xv = x4[d4];
                acc = fmaf(xv.x, e.x, acc);
                acc = fmaf(xv.y, e.y, acc);
                acc = fmaf(xv.z, e.z, acc);
                acc = fmaf(xv.w, e.w, acc);
            }
            float sc = __ldg(&g_ehalf[c]) - acc;
#pragma unroll
            for (int off = 1; off <= 2; off <<= 1) {
                float os = __shfl_xor_sync(0xffffffffu, sc, off);
                int oc = __shfl_xor_sync(0xffffffffu, c, off);
                if (os < sc || (os == sc && oc < c)) { sc = os; c = oc; }
            }
            if ((lane & 3) == 0) {
                g_idx[rowbase + row] = c;
                atomicAdd(&g_counts[c], 1);
            }
        }
    }
}

__global__ void k_gather(const float* __restrict__ inputs, float* __restrict__ out) {
    const int nf4 = N_ROWS * IN_DIM / 4;
    float lsum = 0.f;
    const float4* in4 = (const float4*)inputs;
    float4* out4 = (float4*)out;
    const float4* q4p = (const float4*)g_Qcodes;
    for (int f = blockIdx.x * blockDim.x + threadIdx.x; f < nf4; f += gridDim.x * blockDim.x) {
        int row = f >> 7;
        int col = f & 127;
        int id = __ldg(&g_idx[row]);
        float4 q = q4p[(size_t)id * 128 + col];
        float4 a = in4[f];
        float dx = q.x - a.x, dy = q.y - a.y, dz = q.z - a.z, dw = q.w - a.w;
        out4[f] = make_float4(a.x + dx, a.y + dy, a.z + dz, a.w + dw);
        lsum = fmaf(dx, dx, fmaf(dy, dy, fmaf(dz, dz, fmaf(dw, dw, lsum))));
    }
    for (int o = 16; o > 0; o >>= 1) lsum += __shfl_down_sync(0xffffffffu, lsum, o);
    __shared__ float ws[8];
    int lane = threadIdx.x & 31, w = threadIdx.x >> 5;
    if (lane == 0) ws[w] = lsum;
    __syncthreads();
    if (w == 0) {
        float v = (lane < 8) ? ws[lane] : 0.f;
        for (int o = 4; o > 0; o >>= 1) v += __shfl_down_sync(0xffffffffu, v, o);
        if (lane == 0) atomicAdd(&g_loss, (double)v);
    }
}

__global__ void k_final(float* __restrict__ out, int out_size) {
    __shared__ float red[256];
    int tid = threadIdx.x;
    float s = 0.f;
    for (int i = tid; i < NEMB; i += 256) {
        float p = (float)g_counts[i] * (1.0f / 65536.0f);
        s += p * logf(p + 1e-10f);
    }
    red[tid] = s;
    __syncthreads();
    for (int st = 128; st > 0; st >>= 1) {
        if (tid < st) red[tid] += red[tid + st];
        __syncthreads();
    }
    if (tid == 0) {
        float m = (float)(g_loss * (1.0 / 33554432.0));
        out[out_size - 2] = m + 0.25f * m;
        out[out_size - 1] = expf(-red[0]);
    }
}

extern "C" void kernel_launch(void* const* d_in, const int* in_sizes, int n_in,
                              void* d_out, int out_size) {
    const float* inputs = (const float*)d_in[0];
    const float* emb    = (const float*)d_in[1];
    const float* W_in   = (const float*)d_in[2];
    const float* b_in   = (const float*)d_in[3];
    const float* W_out  = (const float*)d_in[4];
    const float* b_out  = (const float*)d_in[5];
    float* out = (float*)d_out;

    cudaFuncSetAttribute(k_argmin5, cudaFuncAttributeMaxDynamicSharedMemorySize, DYN_SMEM);

    k_prep<<<128, 256>>>(W_in);
    k_codes<<<NEMB / 16, 256>>>(emb, W_out, b_out);
    k_dummy<<<1, 32>>>();                                  // ncu capture-slot shim
    k_argmin5<<<N_ROWS / TILE_M, 128, DYN_SMEM>>>(inputs, b_in, emb);
    k_gather<<<8192, 256>>>(inputs, out);
    k_final<<<1, 256>>>(out, out_size);
}

// round 10
// speedup vs baseline: 1.5293x; 1.1287x over previous
#include <cuda_runtime.h>
#include <cuda_fp16.h>
#include <math.h>
#include <stdint.h>

#define N_ROWS 65536
#define IN_DIM 512
#define NEMB 4096
#define TILE_M 256

__device__ float  g_Qcodes[NEMB * IN_DIM];
__device__ float  g_ehalf[NEMB];
__device__ __half g_emb_f16[NEMB * 64];
__device__ __half g_WinT[64 * 512];          // W_in^T fp16
__device__ float  g_xf[N_ROWS * 64];         // exact fp32 x (for rescore)
__device__ int    g_idx[N_ROWS];
__device__ int    g_counts[NEMB];
__device__ double g_loss;

// ---- smem layout (36864 B) ----
#define SM_B0   0        // screen: codes buf0 [128][72h] pitch 144 -> 18432 ; phase A: A' fp16 [64][272B]
#define SM_B1   18432    // screen: codes buf1                      ; phase A: W' fp16 [64][272B]
#define DYN_SMEM 36864

__device__ __forceinline__ uint32_t smem_u32(const void* p) {
    uint32_t a;
    asm("{ .reg .u64 t; cvta.to.shared.u64 t, %1; cvt.u32.u64 %0, t; }" : "=r"(a) : "l"(p));
    return a;
}
__device__ __forceinline__ void ldmx4(uint32_t r[4], uint32_t addr) {
    asm volatile("ldmatrix.sync.aligned.m8n8.x4.shared.b16 {%0,%1,%2,%3}, [%4];"
        : "=r"(r[0]), "=r"(r[1]), "=r"(r[2]), "=r"(r[3]) : "r"(addr));
}
__device__ __forceinline__ void mma16816(float d[4], const uint32_t a[4], const uint32_t b[2]) {
    asm volatile("mma.sync.aligned.m16n8k16.row.col.f32.f16.f16.f32 "
        "{%0,%1,%2,%3}, {%4,%5,%6,%7}, {%8,%9}, {%0,%1,%2,%3};"
        : "+f"(d[0]), "+f"(d[1]), "+f"(d[2]), "+f"(d[3])
        : "r"(a[0]), "r"(a[1]), "r"(a[2]), "r"(a[3]), "r"(b[0]), "r"(b[1]));
}
__device__ __forceinline__ float packf(float s, int idx) {
    return __uint_as_float((__float_as_uint(s) & 0xFFFFF000u) | (uint32_t)idx);
}
__device__ __forceinline__ uint32_t h2(float a, float b) {
    __half2 h = __floats2half2_rn(a, b);
    return *(uint32_t*)&h;
}
#define CP_ASYNC16(dst, src) \
    asm volatile("cp.async.cg.shared.global [%0], [%1], 16;" :: "r"(dst), "l"(src) : "memory")
#define CP_COMMIT() asm volatile("cp.async.commit_group;" ::: "memory")
#define CP_WAIT(n)  asm volatile("cp.async.wait_group %0;" :: "n"(n) : "memory")

__global__ void k_prep(const float* __restrict__ W_in) {
    int t = blockIdx.x * blockDim.x + threadIdx.x;   // 32768
    if (t < NEMB) g_counts[t] = 0;
    if (t == 0) g_loss = 0.0;
    int n = t >> 9, k = t & 511;
    g_WinT[t] = __float2half(W_in[k * 64 + n]);
}

__global__ void k_dummy() {}   // keeps ncu positional capture on k_argmin

__global__ void k_codes(const float* __restrict__ emb, const float* __restrict__ W_out,
                        const float* __restrict__ b_out) {
    __shared__ float es[16 * 64];
    int tid = threadIdx.x;
    int cb = blockIdx.x * 16;
    for (int i = tid; i < 16 * 64; i += 256) es[i] = emb[(size_t)cb * 64 + i];
    __syncthreads();
    if (tid < 16) {
        float s = 0.f;
        for (int k = 0; k < 64; k++) { float e = es[tid * 64 + k]; s = fmaf(e, e, s); }
        g_ehalf[cb + tid] = 0.5f * s;
    }
    for (int i = tid; i < 16 * 64; i += 256)
        g_emb_f16[(size_t)cb * 64 + i] = __float2half(es[i]);
    float ax[16], ay[16];
#pragma unroll
    for (int c = 0; c < 16; c++) { ax[c] = 0.f; ay[c] = 0.f; }
    int c0 = tid * 2;
    for (int k = 0; k < 64; k++) {
        float2 w = *(const float2*)&W_out[(size_t)k * 512 + c0];
#pragma unroll
        for (int c = 0; c < 16; c++) {
            float e = es[c * 64 + k];
            ax[c] = fmaf(e, w.x, ax[c]);
            ay[c] = fmaf(e, w.y, ay[c]);
        }
    }
    float2 b = *(const float2*)&b_out[c0];
#pragma unroll
    for (int c = 0; c < 16; c++)
        *(float2*)&g_Qcodes[(size_t)(cb + c) * 512 + c0] = make_float2(ax[c] + b.x, ay[c] + b.y);
}

__global__ __launch_bounds__(128, 2) void k_argmin6(
    const float* __restrict__ inputs, const float* __restrict__ b_in,
    const float* __restrict__ emb) {
    extern __shared__ char sm[];
    uint32_t sb = smem_u32(sm);
    int tid = threadIdx.x;
    int wid = tid >> 5;
    int lane = tid & 31;
    int rowbase = blockIdx.x * TILE_M;

    int a_row = (lane & 7) + (lane & 8);
    int a_k8 = ((lane >> 4) & 1) * 8;
    int b_row = (lane & 7) + ((lane >> 4) & 1) * 8;
    int b_k8 = ((lane >> 3) & 1) * 8;

    // ======== Phase A: x = inputs @ W_in + b_in via fp16 MMA, four 64-row quarters ========
    uint32_t A[4][4][4];   // [set(quarter)][kstep][frag]
    int lrow = tid >> 1, lkh = tid & 1;

#pragma unroll 1
    for (int h = 0; h < 4; h++) {
        float d[8][4];
#pragma unroll
        for (int nt = 0; nt < 8; nt++)
#pragma unroll
            for (int j = 0; j < 4; j++) d[nt][j] = 0.f;

        for (int kc = 0; kc < 4; kc++) {
            __syncthreads();
            {
                const float4* gi = (const float4*)(inputs +
                    (size_t)(rowbase + h * 64 + lrow) * 512 + kc * 128 + lkh * 64);
                char* adst = sm + SM_B0 + lrow * 272 + lkh * 128;
#pragma unroll
                for (int j = 0; j < 8; j++) {
                    float4 v0 = gi[2 * j], v1 = gi[2 * j + 1];
                    *(uint4*)(adst + j * 16) =
                        make_uint4(h2(v0.x, v0.y), h2(v0.z, v0.w), h2(v1.x, v1.y), h2(v1.z, v1.w));
                }
            }
            {
                const uint4* gw = (const uint4*)(g_WinT + (size_t)lrow * 512 + kc * 128 + lkh * 64);
                char* wdst = sm + SM_B1 + lrow * 272 + lkh * 128;
#pragma unroll
                for (int j = 0; j < 8; j++) *(uint4*)(wdst + j * 16) = gw[j];
            }
            __syncthreads();
            uint32_t abase = sb + SM_B0 + (uint32_t)(wid * 16 + a_row) * 272 + a_k8 * 2;
            uint32_t bbase = sb + SM_B1 + (uint32_t)b_row * 272 + b_k8 * 2;
#pragma unroll
            for (int ks = 0; ks < 8; ks++) {
                uint32_t Af[4];
                ldmx4(Af, abase + ks * 32);
#pragma unroll
                for (int ng = 0; ng < 4; ng++) {
                    uint32_t Bf[4];
                    ldmx4(Bf, bbase + (uint32_t)ng * (16 * 272) + ks * 32);
                    mma16816(d[ng * 2], Af, Bf + 0);
                    mma16816(d[ng * 2 + 1], Af, Bf + 2);
                }
            }
        }
        // bias add; x fp32 -> global scratch; negated fp16 A-frags (set h)
        {
            int r0 = wid * 16 + (lane >> 2);
            int cbase = (lane & 3) * 2;
#pragma unroll
            for (int nt = 0; nt < 8; nt++) {
                float2 bv = *(const float2*)&b_in[nt * 8 + cbase];
                d[nt][0] += bv.x; d[nt][1] += bv.y;
                d[nt][2] += bv.x; d[nt][3] += bv.y;
                *(float2*)&g_xf[(size_t)(rowbase + h * 64 + r0) * 64 + nt * 8 + cbase] =
                    make_float2(d[nt][0], d[nt][1]);
                *(float2*)&g_xf[(size_t)(rowbase + h * 64 + r0 + 8) * 64 + nt * 8 + cbase] =
                    make_float2(d[nt][2], d[nt][3]);
            }
#pragma unroll
            for (int ks = 0; ks < 4; ks++) {
                A[h][ks][0] = h2(-d[2 * ks][0], -d[2 * ks][1]);
                A[h][ks][1] = h2(-d[2 * ks][2], -d[2 * ks][3]);
                A[h][ks][2] = h2(-d[2 * ks + 1][0], -d[2 * ks + 1][1]);
                A[h][ks][3] = h2(-d[2 * ks + 1][2], -d[2 * ks + 1][3]);
            }
        }
    }
    __syncthreads();   // phase A smem dead

    // ======== stage chunks 0,1 via cp.async ========
    {
        const char* gsrc = (const char*)(g_emb_f16 + (size_t)tid * 64);
        uint32_t sdst = sb + SM_B0 + tid * 144;
#pragma unroll
        for (int j = 0; j < 8; j++) CP_ASYNC16(sdst + j * 16, gsrc + j * 16);
        CP_COMMIT();
        gsrc = (const char*)(g_emb_f16 + (size_t)(128 + tid) * 64);
        sdst = sb + SM_B1 + tid * 144;
#pragma unroll
        for (int j = 0; j < 8; j++) CP_ASYNC16(sdst + j * 16, gsrc + j * 16);
        CP_COMMIT();
    }
    CP_WAIT(1);   // chunk 0 complete
    __syncthreads();

    // ======== Screen: 32 chunks of 128 codes, 64 rows/warp (4 sets) ========
    uint32_t b_lane_off = (uint32_t)b_row * 144 + b_k8 * 2;
    uint32_t bb0 = sb + SM_B0 + b_lane_off;
    uint32_t bb1 = sb + SM_B1 + b_lane_off;
    float pk[8];
#pragma unroll
    for (int j = 0; j < 8; j++) pk[j] = __uint_as_float(0x7F000000u);

#pragma unroll 1
    for (int i = 0; i < 32; i++) {
        uint32_t bb = (i & 1) ? bb1 : bb0;
        int idxbase = i * 128 + (lane & 3) * 2;
#pragma unroll 2
        for (int np = 0; np < 8; np++) {
            float ds[4][2][4];
#pragma unroll
            for (int s = 0; s < 4; s++)
#pragma unroll
                for (int g = 0; g < 2; g++)
#pragma unroll
                    for (int j = 0; j < 4; j++) ds[s][g][j] = 0.f;
            uint32_t baddr = bb + (uint32_t)np * (16 * 144);
#pragma unroll
            for (int k = 0; k < 4; k++) {
                uint32_t B[4];
                ldmx4(B, baddr + k * 32);
#pragma unroll
                for (int s = 0; s < 4; s++) {
                    mma16816(ds[s][0], A[s][k], B + 0);
                    mma16816(ds[s][1], A[s][k], B + 2);
                }
            }
            int c0 = idxbase + np * 16;
            int c1 = c0 + 8;
#pragma unroll
            for (int s = 0; s < 4; s++) {
                pk[s * 2 + 0] = fminf(pk[s * 2 + 0], packf(ds[s][0][0], c0));
                pk[s * 2 + 0] = fminf(pk[s * 2 + 0], packf(ds[s][0][1], c0 + 1));
                pk[s * 2 + 1] = fminf(pk[s * 2 + 1], packf(ds[s][0][2], c0));
                pk[s * 2 + 1] = fminf(pk[s * 2 + 1], packf(ds[s][0][3], c0 + 1));
                pk[s * 2 + 0] = fminf(pk[s * 2 + 0], packf(ds[s][1][0], c1));
                pk[s * 2 + 0] = fminf(pk[s * 2 + 0], packf(ds[s][1][1], c1 + 1));
                pk[s * 2 + 1] = fminf(pk[s * 2 + 1], packf(ds[s][1][2], c1));
                pk[s * 2 + 1] = fminf(pk[s * 2 + 1], packf(ds[s][1][3], c1 + 1));
            }
        }
        __syncthreads();   // all warps done reading buf holding chunk i
        if (i + 2 < 32) {
            const char* gsrc = (const char*)(g_emb_f16 + (size_t)((i + 2) * 128 + tid) * 64);
            uint32_t sdst = sb + ((i & 1) ? SM_B1 : SM_B0) + tid * 144;
#pragma unroll
            for (int j = 0; j < 8; j++) CP_ASYNC16(sdst + j * 16, gsrc + j * 16);
            CP_COMMIT();
            CP_WAIT(1);
        } else {
            CP_WAIT(0);
        }
        __syncthreads();
    }

    // ======== exact fp32 rescore: 4 candidates per row ========
    {
#pragma unroll 1
        for (int sh = 0; sh < 8; sh++) {
            int s = sh >> 1, h = sh & 1;
            float pkv = pk[sh];
            int row = s * 64 + wid * 16 + (lane >> 2) + h * 8;
            int c = (int)(__float_as_uint(pkv) & 0xFFFu);
            const float4* e4 = (const float4*)(emb + (size_t)c * 64);
            const float4* x4 = (const float4*)(g_xf + (size_t)(rowbase + row) * 64);
            float acc = 0.f;
#pragma unroll
            for (int d4 = 0; d4 < 16; d4++) {
                float4 e = e4[d4];
                float4 xv = x4[d4];
                acc = fmaf(xv.x, e.x, acc);
                acc = fmaf(xv.y, e.y, acc);
                acc = fmaf(xv.z, e.z, acc);
                acc = fmaf(xv.w, e.w, acc);
            }
            float sc = __ldg(&g_ehalf[c]) - acc;
#pragma unroll
            for (int off = 1; off <= 2; off <<= 1) {
                float os = __shfl_xor_sync(0xffffffffu, sc, off);
                int oc = __shfl_xor_sync(0xffffffffu, c, off);
                if (os < sc || (os == sc && oc < c)) { sc = os; c = oc; }
            }
            if ((lane & 3) == 0) {
                g_idx[rowbase + row] = c;
                atomicAdd(&g_counts[c], 1);
            }
        }
    }
}

__global__ void k_gather(const float* __restrict__ inputs, float* __restrict__ out) {
    const int nf4 = N_ROWS * IN_DIM / 4;
    float lsum = 0.f;
    const float4* in4 = (const float4*)inputs;
    float4* out4 = (float4*)out;
    const float4* q4p = (const float4*)g_Qcodes;
    for (int f = blockIdx.x * blockDim.x + threadIdx.x; f < nf4; f += gridDim.x * blockDim.x) {
        int row = f >> 7;
        int col = f & 127;
        int id = __ldg(&g_idx[row]);
        float4 q = q4p[(size_t)id * 128 + col];
        float4 a = in4[f];
        float dx = q.x - a.x, dy = q.y - a.y, dz = q.z - a.z, dw = q.w - a.w;
        out4[f] = make_float4(a.x + dx, a.y + dy, a.z + dz, a.w + dw);
        lsum = fmaf(dx, dx, fmaf(dy, dy, fmaf(dz, dz, fmaf(dw, dw, lsum))));
    }
    for (int o = 16; o > 0; o >>= 1) lsum += __shfl_down_sync(0xffffffffu, lsum, o);
    __shared__ float ws[8];
    int lane = threadIdx.x & 31, w = threadIdx.x >> 5;
    if (lane == 0) ws[w] = lsum;
    __syncthreads();
    if (w == 0) {
        float v = (lane < 8) ? ws[lane] : 0.f;
        for (int o = 4; o > 0; o >>= 1) v += __shfl_down_sync(0xffffffffu, v, o);
        if (lane == 0) atomicAdd(&g_loss, (double)v);
    }
}

__global__ void k_final(float* __restrict__ out, int out_size) {
    __shared__ float red[256];
    int tid = threadIdx.x;
    float s = 0.f;
    for (int i = tid; i < NEMB; i += 256) {
        float p = (float)g_counts[i] * (1.0f / 65536.0f);
        s += p * logf(p + 1e-10f);
    }
    red[tid] = s;
    __syncthreads();
    for (int st = 128; st > 0; st >>= 1) {
        if (tid < st) red[tid] += red[tid + st];
        __syncthreads();
    }
    if (tid == 0) {
        float m = (float)(g_loss * (1.0 / 33554432.0));
        out[out_size - 2] = m + 0.25f * m;
        out[out_size - 1] = expf(-red[0]);
    }
}

extern "C" void kernel_launch(void* const* d_in, const int* in_sizes, int n_in,
                              void* d_out, int out_size) {
    const float* inputs = (const float*)d_in[0];
    const float* emb    = (const float*)d_in[1];
    const float* W_in   = (const float*)d_in[2];
    const float* b_in   = (const float*)d_in[3];
    const float* W_out  = (const float*)d_in[4];
    const float* b_out  = (const float*)d_in[5];
    float* out = (float*)d_out;

    cudaFuncSetAttribute(k_argmin6, cudaFuncAttributeMaxDynamicSharedMemorySize, DYN_SMEM);

    k_prep<<<128, 256>>>(W_in);
    k_codes<<<NEMB / 16, 256>>>(emb, W_out, b_out);
    k_dummy<<<1, 32>>>();                                  // ncu capture-slot shim
    k_argmin6<<<N_ROWS / TILE_M, 128, DYN_SMEM>>>(inputs, b_in, emb);
    k_gather<<<8192, 256>>>(inputs, out);
    k_final<<<1, 256>>>(out, out_size);
}